// round 1
// baseline (speedup 1.0000x reference)
#include <cuda_runtime.h>
#include <math.h>

#define NB  8
#define SEQ 2048
#define DIM 512
#define SCALE 0.04419417382415922f  // 1/sqrt(512)

// ---------------------------------------------------------------------------
// GEMM1: logits[b,i,j] = SCALE * sum_d Q[b,i,d] * K[b,j,d]
// 64x64 tile, k-tile 16, 256 threads, 4x4 per thread.
// ---------------------------------------------------------------------------
__global__ __launch_bounds__(256)
void qk_kernel(const float* __restrict__ Q, const float* __restrict__ Km,
               float* __restrict__ attn) {
    __shared__ float As[64][17];   // [row][k]  (reads broadcast across warp)
    __shared__ float Bs[16][68];   // [k][col]  transposed -> float4 reads

    const int b  = blockIdx.z;
    const int i0 = blockIdx.y * 64;
    const int j0 = blockIdx.x * 64;

    const float* q = Q  + (size_t)b * SEQ * DIM;
    const float* k = Km + (size_t)b * SEQ * DIM;
    float* out = attn + (size_t)b * SEQ * SEQ;

    const int tid = threadIdx.x;
    const int tx = tid & 15;       // 0..15
    const int ty = tid >> 4;       // 0..15

    float acc[4][4];
#pragma unroll
    for (int r = 0; r < 4; r++)
#pragma unroll
        for (int c = 0; c < 4; c++) acc[r][c] = 0.0f;

    for (int k0 = 0; k0 < DIM; k0 += 16) {
#pragma unroll
        for (int i = 0; i < 4; i++) {
            int row = ty + i * 16;
            As[row][tx] = q[(size_t)(i0 + row) * DIM + k0 + tx];
            Bs[tx][row] = k[(size_t)(j0 + row) * DIM + k0 + tx];
        }
        __syncthreads();

#pragma unroll
        for (int kk = 0; kk < 16; kk++) {
            float4 bv = *reinterpret_cast<const float4*>(&Bs[kk][tx * 4]);
            float a0 = As[ty * 4 + 0][kk];
            float a1 = As[ty * 4 + 1][kk];
            float a2 = As[ty * 4 + 2][kk];
            float a3 = As[ty * 4 + 3][kk];
            acc[0][0] += a0 * bv.x; acc[0][1] += a0 * bv.y;
            acc[0][2] += a0 * bv.z; acc[0][3] += a0 * bv.w;
            acc[1][0] += a1 * bv.x; acc[1][1] += a1 * bv.y;
            acc[1][2] += a1 * bv.z; acc[1][3] += a1 * bv.w;
            acc[2][0] += a2 * bv.x; acc[2][1] += a2 * bv.y;
            acc[2][2] += a2 * bv.z; acc[2][3] += a2 * bv.w;
            acc[3][0] += a3 * bv.x; acc[3][1] += a3 * bv.y;
            acc[3][2] += a3 * bv.z; acc[3][3] += a3 * bv.w;
        }
        __syncthreads();
    }

#pragma unroll
    for (int r = 0; r < 4; r++) {
        float4 v;
        v.x = acc[r][0] * SCALE;
        v.y = acc[r][1] * SCALE;
        v.z = acc[r][2] * SCALE;
        v.w = acc[r][3] * SCALE;
        *reinterpret_cast<float4*>(
            &out[(size_t)(i0 + ty * 4 + r) * SEQ + j0 + tx * 4]) = v;
    }
}

// ---------------------------------------------------------------------------
// Softmax over each row of 2048, in place. One block (256 thr) per row.
// ---------------------------------------------------------------------------
__global__ __launch_bounds__(256)
void softmax_kernel(float* __restrict__ attn) {
    const size_t row = blockIdx.x;
    float4* p4 = reinterpret_cast<float4*>(attn + row * SEQ);
    const int tid = threadIdx.x;

    float4 v0 = p4[tid];
    float4 v1 = p4[tid + 256];

    float m = fmaxf(fmaxf(fmaxf(v0.x, v0.y), fmaxf(v0.z, v0.w)),
                    fmaxf(fmaxf(v1.x, v1.y), fmaxf(v1.z, v1.w)));
#pragma unroll
    for (int o = 16; o > 0; o >>= 1)
        m = fmaxf(m, __shfl_xor_sync(0xffffffffu, m, o));

    __shared__ float sm[8];
    __shared__ float ss[8];
    if ((tid & 31) == 0) sm[tid >> 5] = m;
    __syncthreads();
    m = sm[0];
#pragma unroll
    for (int i = 1; i < 8; i++) m = fmaxf(m, sm[i]);

    float4 e0, e1;
    e0.x = __expf(v0.x - m); e0.y = __expf(v0.y - m);
    e0.z = __expf(v0.z - m); e0.w = __expf(v0.w - m);
    e1.x = __expf(v1.x - m); e1.y = __expf(v1.y - m);
    e1.z = __expf(v1.z - m); e1.w = __expf(v1.w - m);

    float s = (e0.x + e0.y + e0.z + e0.w) + (e1.x + e1.y + e1.z + e1.w);
#pragma unroll
    for (int o = 16; o > 0; o >>= 1)
        s += __shfl_xor_sync(0xffffffffu, s, o);
    if ((tid & 31) == 0) ss[tid >> 5] = s;
    __syncthreads();
    s = ss[0];
#pragma unroll
    for (int i = 1; i < 8; i++) s += ss[i];

    float inv = 1.0f / s;
    e0.x *= inv; e0.y *= inv; e0.z *= inv; e0.w *= inv;
    e1.x *= inv; e1.y *= inv; e1.z *= inv; e1.w *= inv;
    p4[tid] = e0;
    p4[tid + 256] = e1;
}

// ---------------------------------------------------------------------------
// GEMM2: ctx[b,i,d] = sum_j W[b,i,j] * V[b,j,d]
// 64x64 tile, k-tile 16, 256 threads, 4x4 per thread.
// ---------------------------------------------------------------------------
__global__ __launch_bounds__(256)
void av_kernel(const float* __restrict__ W, const float* __restrict__ V,
               float* __restrict__ ctx) {
    __shared__ float As[64][17];   // [row_i][k]
    __shared__ float Bs[16][64];   // [k][col_d] -> float4 reads

    const int b  = blockIdx.z;
    const int i0 = blockIdx.y * 64;
    const int n0 = blockIdx.x * 64;

    const float* w = W + (size_t)b * SEQ * SEQ;
    const float* v = V + (size_t)b * SEQ * DIM;
    float* o = ctx + (size_t)b * SEQ * DIM;

    const int tid = threadIdx.x;
    const int tx = tid & 15;
    const int ty = tid >> 4;

    float acc[4][4];
#pragma unroll
    for (int r = 0; r < 4; r++)
#pragma unroll
        for (int c = 0; c < 4; c++) acc[r][c] = 0.0f;

    for (int k0 = 0; k0 < SEQ; k0 += 16) {
#pragma unroll
        for (int i = 0; i < 4; i++) {
            int row = ty + i * 16;
            As[row][tx] = w[(size_t)(i0 + row) * SEQ + k0 + tx];
            // Bs[k][n]: each thread loads 4 cols of its k-row
            Bs[ty][tx + i * 16] = v[(size_t)(k0 + ty) * DIM + n0 + tx + i * 16];
        }
        __syncthreads();

#pragma unroll
        for (int kk = 0; kk < 16; kk++) {
            float4 bv = *reinterpret_cast<const float4*>(&Bs[kk][tx * 4]);
            float a0 = As[ty * 4 + 0][kk];
            float a1 = As[ty * 4 + 1][kk];
            float a2 = As[ty * 4 + 2][kk];
            float a3 = As[ty * 4 + 3][kk];
            acc[0][0] += a0 * bv.x; acc[0][1] += a0 * bv.y;
            acc[0][2] += a0 * bv.z; acc[0][3] += a0 * bv.w;
            acc[1][0] += a1 * bv.x; acc[1][1] += a1 * bv.y;
            acc[1][2] += a1 * bv.z; acc[1][3] += a1 * bv.w;
            acc[2][0] += a2 * bv.x; acc[2][1] += a2 * bv.y;
            acc[2][2] += a2 * bv.z; acc[2][3] += a2 * bv.w;
            acc[3][0] += a3 * bv.x; acc[3][1] += a3 * bv.y;
            acc[3][2] += a3 * bv.z; acc[3][3] += a3 * bv.w;
        }
        __syncthreads();
    }

#pragma unroll
    for (int r = 0; r < 4; r++) {
        float4 vv;
        vv.x = acc[r][0]; vv.y = acc[r][1];
        vv.z = acc[r][2]; vv.w = acc[r][3];
        *reinterpret_cast<float4*>(
            &o[(size_t)(i0 + ty * 4 + r) * DIM + n0 + tx * 4]) = vv;
    }
}

// ---------------------------------------------------------------------------
extern "C" void kernel_launch(void* const* d_in, const int* in_sizes, int n_in,
                              void* d_out, int out_size) {
    const float* Q = (const float*)d_in[0];
    const float* K = (const float*)d_in[1];
    const float* V = (const float*)d_in[2];

    float* ctx  = (float*)d_out;                      // [8, 2048, 512]
    float* attn = ctx + (size_t)NB * SEQ * DIM;       // [8, 2048, 2048]

    dim3 g1(SEQ / 64, SEQ / 64, NB);
    qk_kernel<<<g1, 256>>>(Q, K, attn);

    softmax_kernel<<<NB * SEQ, 256>>>(attn);

    dim3 g2(DIM / 64, SEQ / 64, NB);
    av_kernel<<<g2, 256>>>(attn, V, ctx);
}

// round 3
// speedup vs baseline: 3.5794x; 3.5794x over previous
#include <cuda_runtime.h>
#include <math.h>
#include <stdint.h>

#define NB  8
#define SEQ 2048
#define DIM 512
#define SCALE 0.04419417382415922f  // 1/sqrt(512)

// ---------------------------------------------------------------------------
// helpers
// ---------------------------------------------------------------------------
__device__ __forceinline__ uint32_t f2tf(float x) {
    uint32_t u;
    asm("cvt.rna.tf32.f32 %0, %1;" : "=r"(u) : "f"(x));
    return u;
}

__device__ __forceinline__ void mma_tf32(float* d, const uint32_t* a, const uint32_t* b) {
    asm volatile(
        "mma.sync.aligned.m16n8k8.row.col.f32.tf32.tf32.f32 "
        "{%0,%1,%2,%3}, {%4,%5,%6,%7}, {%8,%9}, {%0,%1,%2,%3};\n"
        : "+f"(d[0]), "+f"(d[1]), "+f"(d[2]), "+f"(d[3])
        : "r"(a[0]), "r"(a[1]), "r"(a[2]), "r"(a[3]),
          "r"(b[0]), "r"(b[1]));
}

// ---------------------------------------------------------------------------
// GEMM1: logits[b,i,j] = SCALE * sum_d Q[b,i,d] * K[b,j,d]
// 128x128 tile, BK=32, 256 threads (8 warps, 2x4), warp tile 64x32.
// As[m][k] (pad 36 words), Bs[n][k] (pad 36 words)  — both K-major.
// ---------------------------------------------------------------------------
__global__ __launch_bounds__(256, 2)
void qk_mma_kernel(const float* __restrict__ Q, const float* __restrict__ Km,
                   float* __restrict__ attn) {
    __shared__ uint32_t As[128 * 36];
    __shared__ uint32_t Bs[128 * 36];

    const int b  = blockIdx.z;
    const int i0 = blockIdx.y * 128;
    const int j0 = blockIdx.x * 128;

    const float* q = Q  + (size_t)b * SEQ * DIM;
    const float* k = Km + (size_t)b * SEQ * DIM;
    float* out = attn + (size_t)b * SEQ * SEQ;

    const int tid  = threadIdx.x;
    const int warp = tid >> 5;
    const int lane = tid & 31;
    const int r = lane >> 2;   // group id 0..7
    const int c = lane & 3;    // thread-in-group

    const int wm = (warp & 1) * 64;   // warp m offset
    const int wn = (warp >> 1) * 32;  // warp n offset

    float acc[16][4];
#pragma unroll
    for (int i = 0; i < 16; i++)
#pragma unroll
        for (int j = 0; j < 4; j++) acc[i][j] = 0.0f;

    // per-thread gmem load coords: 4 float4 each for A and B
    // f = tid + i*256 ; row = f>>3 ; c4 = f&7  (tile is 128 rows x 8 float4)
    float4 pa[4], pb[4];

#pragma unroll
    for (int i = 0; i < 4; i++) {
        int f = tid + i * 256;
        int row = f >> 3, c4 = f & 7;
        pa[i] = *reinterpret_cast<const float4*>(&q[(size_t)(i0 + row) * DIM + c4 * 4]);
        pb[i] = *reinterpret_cast<const float4*>(&k[(size_t)(j0 + row) * DIM + c4 * 4]);
    }

    const int NT = DIM / 32;  // 16 k-tiles
    for (int kt = 0; kt < NT; kt++) {
        // store prefetched tile to smem (tf32-converted)
#pragma unroll
        for (int i = 0; i < 4; i++) {
            int f = tid + i * 256;
            int row = f >> 3, c4 = f & 7;
            uint4 ua = make_uint4(f2tf(pa[i].x), f2tf(pa[i].y), f2tf(pa[i].z), f2tf(pa[i].w));
            uint4 ub = make_uint4(f2tf(pb[i].x), f2tf(pb[i].y), f2tf(pb[i].z), f2tf(pb[i].w));
            *reinterpret_cast<uint4*>(&As[row * 36 + c4 * 4]) = ua;
            *reinterpret_cast<uint4*>(&Bs[row * 36 + c4 * 4]) = ub;
        }
        __syncthreads();

        // prefetch next tile
        if (kt + 1 < NT) {
            int k0 = (kt + 1) * 32;
#pragma unroll
            for (int i = 0; i < 4; i++) {
                int f = tid + i * 256;
                int row = f >> 3, c4 = f & 7;
                pa[i] = *reinterpret_cast<const float4*>(&q[(size_t)(i0 + row) * DIM + k0 + c4 * 4]);
                pb[i] = *reinterpret_cast<const float4*>(&k[(size_t)(j0 + row) * DIM + k0 + c4 * 4]);
            }
        }

        // compute 4 k-steps of 8
#pragma unroll
        for (int ks = 0; ks < 4; ks++) {
            uint32_t au[4][4], bu[4][2];
#pragma unroll
            for (int mt = 0; mt < 4; mt++) {
                int rb = wm + mt * 16;
                au[mt][0] = As[(rb + r) * 36 + ks * 8 + c];
                au[mt][1] = As[(rb + r + 8) * 36 + ks * 8 + c];
                au[mt][2] = As[(rb + r) * 36 + ks * 8 + c + 4];
                au[mt][3] = As[(rb + r + 8) * 36 + ks * 8 + c + 4];
            }
#pragma unroll
            for (int nt = 0; nt < 4; nt++) {
                int nb = wn + nt * 8;
                bu[nt][0] = Bs[(nb + r) * 36 + ks * 8 + c];
                bu[nt][1] = Bs[(nb + r) * 36 + ks * 8 + c + 4];
            }
#pragma unroll
            for (int mt = 0; mt < 4; mt++)
#pragma unroll
                for (int nt = 0; nt < 4; nt++)
                    mma_tf32(acc[mt * 4 + nt], au[mt], bu[nt]);
        }
        __syncthreads();
    }

    // epilogue: scale + store
#pragma unroll
    for (int mt = 0; mt < 4; mt++) {
#pragma unroll
        for (int nt = 0; nt < 4; nt++) {
            float* a = acc[mt * 4 + nt];
            int row = i0 + wm + mt * 16 + r;
            int col = j0 + wn + nt * 8 + c * 2;
            float2 v0 = make_float2(a[0] * SCALE, a[1] * SCALE);
            float2 v1 = make_float2(a[2] * SCALE, a[3] * SCALE);
            *reinterpret_cast<float2*>(&out[(size_t)row * SEQ + col]) = v0;
            *reinterpret_cast<float2*>(&out[(size_t)(row + 8) * SEQ + col]) = v1;
        }
    }
}

// ---------------------------------------------------------------------------
// Softmax over each row of 2048, in place. One block (256 thr) per row.
// ---------------------------------------------------------------------------
__global__ __launch_bounds__(256)
void softmax_kernel(float* __restrict__ attn) {
    const size_t row = blockIdx.x;
    float4* p4 = reinterpret_cast<float4*>(attn + row * SEQ);
    const int tid = threadIdx.x;

    float4 v0 = p4[tid];
    float4 v1 = p4[tid + 256];

    float m = fmaxf(fmaxf(fmaxf(v0.x, v0.y), fmaxf(v0.z, v0.w)),
                    fmaxf(fmaxf(v1.x, v1.y), fmaxf(v1.z, v1.w)));
#pragma unroll
    for (int o = 16; o > 0; o >>= 1)
        m = fmaxf(m, __shfl_xor_sync(0xffffffffu, m, o));

    __shared__ float sm[8];
    __shared__ float ss[8];
    if ((tid & 31) == 0) sm[tid >> 5] = m;
    __syncthreads();
    m = sm[0];
#pragma unroll
    for (int i = 1; i < 8; i++) m = fmaxf(m, sm[i]);

    float4 e0, e1;
    e0.x = __expf(v0.x - m); e0.y = __expf(v0.y - m);
    e0.z = __expf(v0.z - m); e0.w = __expf(v0.w - m);
    e1.x = __expf(v1.x - m); e1.y = __expf(v1.y - m);
    e1.z = __expf(v1.z - m); e1.w = __expf(v1.w - m);

    float s = (e0.x + e0.y + e0.z + e0.w) + (e1.x + e1.y + e1.z + e1.w);
#pragma unroll
    for (int o = 16; o > 0; o >>= 1)
        s += __shfl_xor_sync(0xffffffffu, s, o);
    if ((tid & 31) == 0) ss[tid >> 5] = s;
    __syncthreads();
    s = ss[0];
#pragma unroll
    for (int i = 1; i < 8; i++) s += ss[i];

    float inv = 1.0f / s;
    e0.x *= inv; e0.y *= inv; e0.z *= inv; e0.w *= inv;
    e1.x *= inv; e1.y *= inv; e1.z *= inv; e1.w *= inv;
    p4[tid] = e0;
    p4[tid + 256] = e1;
}

// ---------------------------------------------------------------------------
// GEMM2: ctx[b,i,d] = sum_j W[b,i,j] * V[b,j,d]
// 128x128 tile, BK=32. As[m][k] pad 36; Bs[k][n] pad 132 (N-major).
// ---------------------------------------------------------------------------
__global__ __launch_bounds__(256, 2)
void av_mma_kernel(const float* __restrict__ W, const float* __restrict__ V,
                   float* __restrict__ ctx) {
    __shared__ uint32_t As[128 * 36];
    __shared__ uint32_t Bs[32 * 132];

    const int b  = blockIdx.z;
    const int i0 = blockIdx.y * 128;
    const int n0 = blockIdx.x * 128;

    const float* w = W + (size_t)b * SEQ * SEQ;
    const float* v = V + (size_t)b * SEQ * DIM;
    float* o = ctx + (size_t)b * SEQ * DIM;

    const int tid  = threadIdx.x;
    const int warp = tid >> 5;
    const int lane = tid & 31;
    const int r = lane >> 2;
    const int c = lane & 3;

    const int wm = (warp & 1) * 64;
    const int wn = (warp >> 1) * 32;

    float acc[16][4];
#pragma unroll
    for (int i = 0; i < 16; i++)
#pragma unroll
        for (int j = 0; j < 4; j++) acc[i][j] = 0.0f;

    float4 pa[4], pb[4];

    // A tile: 128 rows x 8 float4 (k); B tile: 32 rows (k) x 32 float4 (n)
#pragma unroll
    for (int i = 0; i < 4; i++) {
        int f = tid + i * 256;
        int arow = f >> 3, ac4 = f & 7;
        pa[i] = *reinterpret_cast<const float4*>(&w[(size_t)(i0 + arow) * SEQ + ac4 * 4]);
        int brow = f >> 5, bc4 = f & 31;
        pb[i] = *reinterpret_cast<const float4*>(&v[(size_t)brow * DIM + n0 + bc4 * 4]);
    }

    const int NT = SEQ / 32;  // 64 k-tiles
    for (int kt = 0; kt < NT; kt++) {
#pragma unroll
        for (int i = 0; i < 4; i++) {
            int f = tid + i * 256;
            int arow = f >> 3, ac4 = f & 7;
            uint4 ua = make_uint4(f2tf(pa[i].x), f2tf(pa[i].y), f2tf(pa[i].z), f2tf(pa[i].w));
            *reinterpret_cast<uint4*>(&As[arow * 36 + ac4 * 4]) = ua;
            int brow = f >> 5, bc4 = f & 31;
            uint4 ub = make_uint4(f2tf(pb[i].x), f2tf(pb[i].y), f2tf(pb[i].z), f2tf(pb[i].w));
            *reinterpret_cast<uint4*>(&Bs[brow * 132 + bc4 * 4]) = ub;
        }
        __syncthreads();

        if (kt + 1 < NT) {
            int k0 = (kt + 1) * 32;
#pragma unroll
            for (int i = 0; i < 4; i++) {
                int f = tid + i * 256;
                int arow = f >> 3, ac4 = f & 7;
                pa[i] = *reinterpret_cast<const float4*>(&w[(size_t)(i0 + arow) * SEQ + k0 + ac4 * 4]);
                int brow = f >> 5, bc4 = f & 31;
                pb[i] = *reinterpret_cast<const float4*>(&v[(size_t)(k0 + brow) * DIM + n0 + bc4 * 4]);
            }
        }

#pragma unroll
        for (int ks = 0; ks < 4; ks++) {
            uint32_t au[4][4], bu[4][2];
#pragma unroll
            for (int mt = 0; mt < 4; mt++) {
                int rb = wm + mt * 16;
                au[mt][0] = As[(rb + r) * 36 + ks * 8 + c];
                au[mt][1] = As[(rb + r + 8) * 36 + ks * 8 + c];
                au[mt][2] = As[(rb + r) * 36 + ks * 8 + c + 4];
                au[mt][3] = As[(rb + r + 8) * 36 + ks * 8 + c + 4];
            }
#pragma unroll
            for (int nt = 0; nt < 4; nt++) {
                int nb = wn + nt * 8;
                bu[nt][0] = Bs[(ks * 8 + c) * 132 + nb + r];
                bu[nt][1] = Bs[(ks * 8 + c + 4) * 132 + nb + r];
            }
#pragma unroll
            for (int mt = 0; mt < 4; mt++)
#pragma unroll
                for (int nt = 0; nt < 4; nt++)
                    mma_tf32(acc[mt * 4 + nt], au[mt], bu[nt]);
        }
        __syncthreads();
    }

#pragma unroll
    for (int mt = 0; mt < 4; mt++) {
#pragma unroll
        for (int nt = 0; nt < 4; nt++) {
            float* a = acc[mt * 4 + nt];
            int row = i0 + wm + mt * 16 + r;
            int col = n0 + wn + nt * 8 + c * 2;
            float2 v0 = make_float2(a[0], a[1]);
            float2 v1 = make_float2(a[2], a[3]);
            *reinterpret_cast<float2*>(&o[(size_t)row * DIM + col]) = v0;
            *reinterpret_cast<float2*>(&o[(size_t)(row + 8) * DIM + col]) = v1;
        }
    }
}

// ---------------------------------------------------------------------------
extern "C" void kernel_launch(void* const* d_in, const int* in_sizes, int n_in,
                              void* d_out, int out_size) {
    const float* Q = (const float*)d_in[0];
    const float* K = (const float*)d_in[1];
    const float* V = (const float*)d_in[2];

    float* ctx  = (float*)d_out;                      // [8, 2048, 512]
    float* attn = ctx + (size_t)NB * SEQ * DIM;       // [8, 2048, 2048]

    dim3 g1(SEQ / 128, SEQ / 128, NB);
    qk_mma_kernel<<<g1, 256>>>(Q, K, attn);

    softmax_kernel<<<NB * SEQ, 256>>>(attn);

    dim3 g2(DIM / 128, SEQ / 128, NB);
    av_mma_kernel<<<g2, 256>>>(attn, V, ctx);
}

// round 5
// speedup vs baseline: 3.6980x; 1.0331x over previous
#include <cuda_runtime.h>
#include <math.h>
#include <stdint.h>

#define NB  8
#define SEQ 2048
#define DIM 512
#define SCALE 0.04419417382415922f  // 1/sqrt(512)

// tf32-rounded copies of the GEMM inputs (pre-pass), so the GEMM kernels can
// feed raw f32 bits to mma.sync with zero conversion work.
__device__ float g_Qr[(size_t)NB * SEQ * DIM];
__device__ float g_Kr[(size_t)NB * SEQ * DIM];
__device__ float g_Vr[(size_t)NB * SEQ * DIM];

// ---------------------------------------------------------------------------
// helpers
// ---------------------------------------------------------------------------
__device__ __forceinline__ uint32_t f2tf(float x) {
    uint32_t u;
    asm("cvt.rna.tf32.f32 %0, %1;" : "=r"(u) : "f"(x));
    return u;
}
__device__ __forceinline__ float f2tf_f(float x) {
    return __uint_as_float(f2tf(x));
}

__device__ __forceinline__ uint32_t smem_u32(const void* p) {
    uint32_t a;
    asm("{ .reg .u64 t; cvta.to.shared.u64 t, %1; cvt.u32.u64 %0, t; }"
        : "=r"(a) : "l"(p));
    return a;
}

#define CP_ASYNC16(dst_u32, src_ptr) \
    asm volatile("cp.async.cg.shared.global [%0], [%1], 16;" \
                 :: "r"(dst_u32), "l"(src_ptr) : "memory")
#define CP_COMMIT() asm volatile("cp.async.commit_group;" ::: "memory")
#define CP_WAIT1()  asm volatile("cp.async.wait_group 1;" ::: "memory")

__device__ __forceinline__ void mma_tf32(float* d, const uint32_t* a, const uint32_t* b) {
    asm volatile(
        "mma.sync.aligned.m16n8k8.row.col.f32.tf32.tf32.f32 "
        "{%0,%1,%2,%3}, {%4,%5,%6,%7}, {%8,%9}, {%0,%1,%2,%3};\n"
        : "+f"(d[0]), "+f"(d[1]), "+f"(d[2]), "+f"(d[3])
        : "r"(a[0]), "r"(a[1]), "r"(a[2]), "r"(a[3]),
          "r"(b[0]), "r"(b[1]));
}

// ---------------------------------------------------------------------------
// tf32 rounding pre-pass
// ---------------------------------------------------------------------------
__global__ __launch_bounds__(256)
void round_tf32_kernel(const float* __restrict__ in, float* __restrict__ out) {
    int i = blockIdx.x * 256 + threadIdx.x;
    float4 v = reinterpret_cast<const float4*>(in)[i];
    v.x = f2tf_f(v.x); v.y = f2tf_f(v.y);
    v.z = f2tf_f(v.z); v.w = f2tf_f(v.w);
    reinterpret_cast<float4*>(out)[i] = v;
}

// ---------------------------------------------------------------------------
// GEMM1: logits[b,i,j] = SCALE * sum_d Qr[b,i,d] * Kr[b,j,d]
// 128x128 tile, BK=32, 3-stage cp.async pipeline, 256 threads (8 warps),
// warp tile 64x32 (2x4), 4x4 m16n8k8 tf32 tiles.
// smem rows padded to 36 words (144B, 16B-aligned, conflict-free reads).
// ---------------------------------------------------------------------------
#define QK_TW 4608  // words per tile per stage: 128*36

__global__ __launch_bounds__(256)
void qk_mma_kernel(const float* __restrict__ Q, const float* __restrict__ Km,
                   float* __restrict__ attn) {
    extern __shared__ __align__(16) uint32_t sh[];
    uint32_t* As = sh;                // 3 stages
    uint32_t* Bs = sh + 3 * QK_TW;    // 3 stages
    const uint32_t as_b = smem_u32(As);
    const uint32_t bs_b = smem_u32(Bs);

    const int b  = blockIdx.z;
    const int i0 = blockIdx.y * 128;
    const int j0 = blockIdx.x * 128;

    const float* q = Q  + (size_t)b * SEQ * DIM + (size_t)i0 * DIM;
    const float* k = Km + (size_t)b * SEQ * DIM + (size_t)j0 * DIM;
    float* out = attn + (size_t)b * SEQ * SEQ;

    const int tid  = threadIdx.x;
    const int warp = tid >> 5;
    const int lane = tid & 31;
    const int r = lane >> 2;
    const int c = lane & 3;
    const int wm = (warp & 1) * 64;
    const int wn = (warp >> 1) * 32;

    // per-thread load slots
    int lrow[4], lc4[4];
#pragma unroll
    for (int t = 0; t < 4; t++) {
        int f = tid + t * 256;
        lrow[t] = f >> 3;
        lc4[t]  = f & 7;
    }

    float acc[16][4];
#pragma unroll
    for (int i = 0; i < 16; i++)
#pragma unroll
        for (int j = 0; j < 4; j++) acc[i][j] = 0.0f;

    const int NT = DIM / 32;  // 16 chunks

    // prologue: issue chunks 0,1
#pragma unroll
    for (int pc = 0; pc < 2; pc++) {
#pragma unroll
        for (int t = 0; t < 4; t++) {
            uint32_t so = (pc * QK_TW + lrow[t] * 36 + lc4[t] * 4) * 4;
            CP_ASYNC16(as_b + so, &q[(size_t)lrow[t] * DIM + pc * 32 + lc4[t] * 4]);
            CP_ASYNC16(bs_b + so, &k[(size_t)lrow[t] * DIM + pc * 32 + lc4[t] * 4]);
        }
        CP_COMMIT();
    }

    for (int kt = 0; kt < NT; kt++) {
        const int s = kt % 3;
        CP_WAIT1();
        __syncthreads();

        // issue chunk kt+2 into stage (kt+2)%3 (safe: past barrier)
        if (kt + 2 < NT) {
            const int s2 = (kt + 2) % 3;
            const int k0 = (kt + 2) * 32;
#pragma unroll
            for (int t = 0; t < 4; t++) {
                uint32_t so = (s2 * QK_TW + lrow[t] * 36 + lc4[t] * 4) * 4;
                CP_ASYNC16(as_b + so, &q[(size_t)lrow[t] * DIM + k0 + lc4[t] * 4]);
                CP_ASYNC16(bs_b + so, &k[(size_t)lrow[t] * DIM + k0 + lc4[t] * 4]);
            }
        }
        CP_COMMIT();

        const uint32_t* Ast = As + s * QK_TW;
        const uint32_t* Bst = Bs + s * QK_TW;
#pragma unroll
        for (int ks = 0; ks < 4; ks++) {
            uint32_t au[4][4], bu[4][2];
#pragma unroll
            for (int mt = 0; mt < 4; mt++) {
                int rb = wm + mt * 16;
                au[mt][0] = Ast[(rb + r) * 36 + ks * 8 + c];
                au[mt][1] = Ast[(rb + r + 8) * 36 + ks * 8 + c];
                au[mt][2] = Ast[(rb + r) * 36 + ks * 8 + c + 4];
                au[mt][3] = Ast[(rb + r + 8) * 36 + ks * 8 + c + 4];
            }
#pragma unroll
            for (int nt = 0; nt < 4; nt++) {
                int nb = wn + nt * 8;
                bu[nt][0] = Bst[(nb + r) * 36 + ks * 8 + c];
                bu[nt][1] = Bst[(nb + r) * 36 + ks * 8 + c + 4];
            }
#pragma unroll
            for (int mt = 0; mt < 4; mt++)
#pragma unroll
                for (int nt = 0; nt < 4; nt++)
                    mma_tf32(acc[mt * 4 + nt], au[mt], bu[nt]);
        }
    }

#pragma unroll
    for (int mt = 0; mt < 4; mt++) {
#pragma unroll
        for (int nt = 0; nt < 4; nt++) {
            float* a = acc[mt * 4 + nt];
            int row = i0 + wm + mt * 16 + r;
            int col = j0 + wn + nt * 8 + c * 2;
            float2 v0 = make_float2(a[0] * SCALE, a[1] * SCALE);
            float2 v1 = make_float2(a[2] * SCALE, a[3] * SCALE);
            *reinterpret_cast<float2*>(&out[(size_t)row * SEQ + col]) = v0;
            *reinterpret_cast<float2*>(&out[(size_t)(row + 8) * SEQ + col]) = v1;
        }
    }
}

// ---------------------------------------------------------------------------
// Softmax over each row of 2048, in place; output rounded to tf32 so GEMM2
// can consume raw bits.
// ---------------------------------------------------------------------------
__global__ __launch_bounds__(256)
void softmax_kernel(float* __restrict__ attn) {
    const size_t row = blockIdx.x;
    float4* p4 = reinterpret_cast<float4*>(attn + row * SEQ);
    const int tid = threadIdx.x;

    float4 v0 = p4[tid];
    float4 v1 = p4[tid + 256];

    float m = fmaxf(fmaxf(fmaxf(v0.x, v0.y), fmaxf(v0.z, v0.w)),
                    fmaxf(fmaxf(v1.x, v1.y), fmaxf(v1.z, v1.w)));
#pragma unroll
    for (int o = 16; o > 0; o >>= 1)
        m = fmaxf(m, __shfl_xor_sync(0xffffffffu, m, o));

    __shared__ float sm[8];
    __shared__ float ss[8];
    if ((tid & 31) == 0) sm[tid >> 5] = m;
    __syncthreads();
    m = sm[0];
#pragma unroll
    for (int i = 1; i < 8; i++) m = fmaxf(m, sm[i]);

    float4 e0, e1;
    e0.x = __expf(v0.x - m); e0.y = __expf(v0.y - m);
    e0.z = __expf(v0.z - m); e0.w = __expf(v0.w - m);
    e1.x = __expf(v1.x - m); e1.y = __expf(v1.y - m);
    e1.z = __expf(v1.z - m); e1.w = __expf(v1.w - m);

    float s = (e0.x + e0.y + e0.z + e0.w) + (e1.x + e1.y + e1.z + e1.w);
#pragma unroll
    for (int o = 16; o > 0; o >>= 1)
        s += __shfl_xor_sync(0xffffffffu, s, o);
    if ((tid & 31) == 0) ss[tid >> 5] = s;
    __syncthreads();
    s = ss[0];
#pragma unroll
    for (int i = 1; i < 8; i++) s += ss[i];

    float inv = 1.0f / s;
    e0.x = f2tf_f(e0.x * inv); e0.y = f2tf_f(e0.y * inv);
    e0.z = f2tf_f(e0.z * inv); e0.w = f2tf_f(e0.w * inv);
    e1.x = f2tf_f(e1.x * inv); e1.y = f2tf_f(e1.y * inv);
    e1.z = f2tf_f(e1.z * inv); e1.w = f2tf_f(e1.w * inv);
    p4[tid] = e0;
    p4[tid + 256] = e1;
}

// ---------------------------------------------------------------------------
// GEMM2: ctx[b,i,d] = sum_j W[b,i,j] * Vr[b,j,d]
// 128x128 tile, BK=32, 3-stage cp.async pipeline.
// A: [m][k] pad 36;  B: [k][n] pad 132 (N-major).
// ---------------------------------------------------------------------------
#define AV_AW 4608   // 128*36
#define AV_BW 4224   // 32*132

__global__ __launch_bounds__(256)
void av_mma_kernel(const float* __restrict__ W, const float* __restrict__ V,
                   float* __restrict__ ctx) {
    extern __shared__ __align__(16) uint32_t sh[];
    uint32_t* As = sh;                 // 3 stages of AV_AW
    uint32_t* Bs = sh + 3 * AV_AW;     // 3 stages of AV_BW
    const uint32_t as_b = smem_u32(As);
    const uint32_t bs_b = smem_u32(Bs);

    const int b  = blockIdx.z;
    const int i0 = blockIdx.y * 128;
    const int n0 = blockIdx.x * 128;

    const float* w = W + (size_t)b * SEQ * SEQ + (size_t)i0 * SEQ;
    const float* v = V + (size_t)b * SEQ * DIM;
    float* o = ctx + (size_t)b * SEQ * DIM;

    const int tid  = threadIdx.x;
    const int warp = tid >> 5;
    const int lane = tid & 31;
    const int r = lane >> 2;
    const int c = lane & 3;
    const int wm = (warp & 1) * 64;
    const int wn = (warp >> 1) * 32;

    int arow[4], ac4[4], brow[4], bc4[4];
#pragma unroll
    for (int t = 0; t < 4; t++) {
        int f = tid + t * 256;
        arow[t] = f >> 3;  ac4[t] = f & 7;
        brow[t] = f >> 5;  bc4[t] = f & 31;
    }

    float acc[16][4];
#pragma unroll
    for (int i = 0; i < 16; i++)
#pragma unroll
        for (int j = 0; j < 4; j++) acc[i][j] = 0.0f;

    const int NT = SEQ / 32;  // 64 chunks

#pragma unroll
    for (int pc = 0; pc < 2; pc++) {
#pragma unroll
        for (int t = 0; t < 4; t++) {
            uint32_t sa = (pc * AV_AW + arow[t] * 36 + ac4[t] * 4) * 4;
            CP_ASYNC16(as_b + sa, &w[(size_t)arow[t] * SEQ + pc * 32 + ac4[t] * 4]);
            uint32_t sb = (3 * AV_AW * 0 + pc * AV_BW + brow[t] * 132 + bc4[t] * 4) * 4;
            CP_ASYNC16(bs_b + sb, &v[(size_t)(pc * 32 + brow[t]) * DIM + n0 + bc4[t] * 4]);
        }
        CP_COMMIT();
    }

    for (int kt = 0; kt < NT; kt++) {
        const int s = kt % 3;
        CP_WAIT1();
        __syncthreads();

        if (kt + 2 < NT) {
            const int s2 = (kt + 2) % 3;
            const int k0 = (kt + 2) * 32;
#pragma unroll
            for (int t = 0; t < 4; t++) {
                uint32_t sa = (s2 * AV_AW + arow[t] * 36 + ac4[t] * 4) * 4;
                CP_ASYNC16(as_b + sa, &w[(size_t)arow[t] * SEQ + k0 + ac4[t] * 4]);
                uint32_t sb = (s2 * AV_BW + brow[t] * 132 + bc4[t] * 4) * 4;
                CP_ASYNC16(bs_b + sb, &v[(size_t)(k0 + brow[t]) * DIM + n0 + bc4[t] * 4]);
            }
        }
        CP_COMMIT();

        const uint32_t* Ast = As + s * AV_AW;
        const uint32_t* Bst = Bs + s * AV_BW;
#pragma unroll
        for (int ks = 0; ks < 4; ks++) {
            uint32_t au[4][4], bu[4][2];
#pragma unroll
            for (int mt = 0; mt < 4; mt++) {
                int rb = wm + mt * 16;
                au[mt][0] = Ast[(rb + r) * 36 + ks * 8 + c];
                au[mt][1] = Ast[(rb + r + 8) * 36 + ks * 8 + c];
                au[mt][2] = Ast[(rb + r) * 36 + ks * 8 + c + 4];
                au[mt][3] = Ast[(rb + r + 8) * 36 + ks * 8 + c + 4];
            }
#pragma unroll
            for (int nt = 0; nt < 4; nt++) {
                int nb = wn + nt * 8;
                bu[nt][0] = Bst[(ks * 8 + c) * 132 + nb + r];
                bu[nt][1] = Bst[(ks * 8 + c + 4) * 132 + nb + r];
            }
#pragma unroll
            for (int mt = 0; mt < 4; mt++)
#pragma unroll
                for (int nt = 0; nt < 4; nt++)
                    mma_tf32(acc[mt * 4 + nt], au[mt], bu[nt]);
        }
    }

#pragma unroll
    for (int mt = 0; mt < 4; mt++) {
#pragma unroll
        for (int nt = 0; nt < 4; nt++) {
            float* a = acc[mt * 4 + nt];
            int row = i0 + wm + mt * 16 + r;
            int col = n0 + wn + nt * 8 + c * 2;
            float2 v0 = make_float2(a[0], a[1]);
            float2 v1 = make_float2(a[2], a[3]);
            *reinterpret_cast<float2*>(&o[(size_t)row * DIM + col]) = v0;
            *reinterpret_cast<float2*>(&o[(size_t)(row + 8) * DIM + col]) = v1;
        }
    }
}

// ---------------------------------------------------------------------------
extern "C" void kernel_launch(void* const* d_in, const int* in_sizes, int n_in,
                              void* d_out, int out_size) {
    const float* Q = (const float*)d_in[0];
    const float* K = (const float*)d_in[1];
    const float* V = (const float*)d_in[2];

    float* ctx  = (float*)d_out;                      // [8, 2048, 512]
    float* attn = ctx + (size_t)NB * SEQ * DIM;       // [8, 2048, 2048]

    float *Qr, *Kr, *Vr;
    cudaGetSymbolAddress((void**)&Qr, g_Qr);
    cudaGetSymbolAddress((void**)&Kr, g_Kr);
    cudaGetSymbolAddress((void**)&Vr, g_Vr);

    constexpr int QK_SMEM = 3 * QK_TW * 2 * 4;             // 110592 B
    constexpr int AV_SMEM = 3 * (AV_AW + AV_BW) * 4;       // 105984 B
    cudaFuncSetAttribute(qk_mma_kernel,
                         cudaFuncAttributeMaxDynamicSharedMemorySize, QK_SMEM);
    cudaFuncSetAttribute(av_mma_kernel,
                         cudaFuncAttributeMaxDynamicSharedMemorySize, AV_SMEM);

    const int n4 = NB * SEQ * DIM / 4;  // 2M float4 per tensor
    round_tf32_kernel<<<n4 / 256, 256>>>(Q, Qr);
    round_tf32_kernel<<<n4 / 256, 256>>>(K, Kr);
    round_tf32_kernel<<<n4 / 256, 256>>>(V, Vr);

    dim3 g1(SEQ / 128, SEQ / 128, NB);
    qk_mma_kernel<<<g1, 256, QK_SMEM>>>(Qr, Kr, attn);

    softmax_kernel<<<NB * SEQ, 256>>>(attn);

    dim3 g2(DIM / 128, SEQ / 128, NB);
    av_mma_kernel<<<g2, 256, AV_SMEM>>>(attn, Vr, ctx);
}